// round 2
// baseline (speedup 1.0000x reference)
#include <cuda_runtime.h>
#include <math.h>
#include <stdint.h>
#include <stddef.h>

#define D_MODEL 1024
#define NUM_HEADS 16
#define DEPTH 64
#define BATCH 2
#define SEQ 2048
#define BS_ROWS (BATCH * SEQ)      /* 4096 */
#define NEG_INF_F (-1e9f)

// ---------------------------------------------------------------------------
// Scratch (allocation-free rule: __device__ globals)
// ---------------------------------------------------------------------------
__device__ float g_Q[(size_t)BS_ROWS * D_MODEL];
__device__ float g_K[(size_t)BS_ROWS * D_MODEL];
__device__ float g_V[(size_t)BS_ROWS * D_MODEL];
__device__ float g_ctx[(size_t)BS_ROWS * D_MODEL];
// Fallback attn scratch if harness output doesn't include the attn tensor.
__device__ float g_attn[(size_t)BATCH * NUM_HEADS * SEQ * SEQ];

// ---------------------------------------------------------------------------
// SGEMM: C[M,N] = A[M,K] @ B[K,N] + bias[N]   (all row-major, fp32)
// BM=128, BN=128, BK=8, 256 threads, 8x8 per thread.
// Assumes M%128==0, N%128==0, K%8==0.
// ---------------------------------------------------------------------------
__global__ __launch_bounds__(256) void sgemm_bias_kernel(
    const float* __restrict__ A, const float* __restrict__ B,
    const float* __restrict__ bias, float* __restrict__ C,
    int M, int N, int K)
{
    const int BM = 128, BN = 128, BK = 8;
    __shared__ __align__(16) float As[BK][BM];
    __shared__ __align__(16) float Bs[BK][BN];

    const int tid = threadIdx.x;
    const int m0 = blockIdx.y * BM;
    const int n0 = blockIdx.x * BN;
    const int tx = tid & 15;       // 0..15 -> col group
    const int ty = tid >> 4;       // 0..15 -> row group

    // A tile load mapping: 128 rows x 8 k, one float4 per thread
    const int aRow = tid >> 1;          // 0..127
    const int aCol = (tid & 1) * 4;     // 0 or 4
    // B tile load mapping: 8 k-rows x 128 cols, one float4 per thread
    const int bRow = tid >> 5;          // 0..7
    const int bCol = (tid & 31) * 4;    // 0..124

    const float* Aptr = A + (size_t)(m0 + aRow) * K + aCol;
    const float* Bptr = B + (size_t)bRow * N + n0 + bCol;

    float acc[8][8];
#pragma unroll
    for (int i = 0; i < 8; i++)
#pragma unroll
        for (int j = 0; j < 8; j++) acc[i][j] = 0.0f;

    for (int k0 = 0; k0 < K; k0 += BK) {
        float4 av = *(const float4*)(Aptr + k0);
        As[aCol + 0][aRow] = av.x;
        As[aCol + 1][aRow] = av.y;
        As[aCol + 2][aRow] = av.z;
        As[aCol + 3][aRow] = av.w;
        float4 bv = *(const float4*)(Bptr + (size_t)k0 * N);
        *(float4*)&Bs[bRow][bCol] = bv;
        __syncthreads();

#pragma unroll
        for (int k = 0; k < BK; k++) {
            float4 a0 = *(const float4*)&As[k][ty * 8];
            float4 a1 = *(const float4*)&As[k][ty * 8 + 4];
            float4 b0 = *(const float4*)&Bs[k][tx * 8];
            float4 b1 = *(const float4*)&Bs[k][tx * 8 + 4];
            float ar[8] = {a0.x, a0.y, a0.z, a0.w, a1.x, a1.y, a1.z, a1.w};
            float br[8] = {b0.x, b0.y, b0.z, b0.w, b1.x, b1.y, b1.z, b1.w};
#pragma unroll
            for (int i = 0; i < 8; i++)
#pragma unroll
                for (int j = 0; j < 8; j++)
                    acc[i][j] = fmaf(ar[i], br[j], acc[i][j]);
        }
        __syncthreads();
    }

#pragma unroll
    for (int i = 0; i < 8; i++) {
        const int row = m0 + ty * 8 + i;
#pragma unroll
        for (int j = 0; j < 8; j += 4) {
            const int col = n0 + tx * 8 + j;
            float4 o;
            o.x = acc[i][j + 0] + bias[col + 0];
            o.y = acc[i][j + 1] + bias[col + 1];
            o.z = acc[i][j + 2] + bias[col + 2];
            o.w = acc[i][j + 3] + bias[col + 3];
            *(float4*)&C[(size_t)row * N + col] = o;
        }
    }
}

// ---------------------------------------------------------------------------
// Logits: per (b,h): L[i,j] = scale * sum_d Qh[i,d]*Kh[j,d] + mask[b,j]*NEG_INF
// A,B are [SEQ, DEPTH] slices with row stride D_MODEL. BM=BN=128, BK=8.
// ---------------------------------------------------------------------------
__global__ __launch_bounds__(256) void logits_kernel(
    const float* __restrict__ Q, const float* __restrict__ K,
    const int* __restrict__ mask, float* __restrict__ attn, float scale)
{
    const int BM = 128, BN = 128, BK = 8;
    __shared__ __align__(16) float As[BK][BM];
    __shared__ __align__(16) float Bs[BK][BN];

    const int bh = blockIdx.z;
    const int b = bh / NUM_HEADS;
    const int h = bh % NUM_HEADS;
    const float* Qh = Q + (size_t)b * SEQ * D_MODEL + h * DEPTH;
    const float* Kh = K + (size_t)b * SEQ * D_MODEL + h * DEPTH;
    float* Cb = attn + (size_t)bh * SEQ * SEQ;

    const int m0 = blockIdx.y * BM;
    const int n0 = blockIdx.x * BN;
    const int tid = threadIdx.x;
    const int tx = tid & 15;
    const int ty = tid >> 4;
    const int lRow = tid >> 1;          // 0..127
    const int lCol = (tid & 1) * 4;     // 0 or 4

    float acc[8][8];
#pragma unroll
    for (int i = 0; i < 8; i++)
#pragma unroll
        for (int j = 0; j < 8; j++) acc[i][j] = 0.0f;

    for (int k0 = 0; k0 < DEPTH; k0 += BK) {
        float4 av = *(const float4*)(Qh + (size_t)(m0 + lRow) * D_MODEL + k0 + lCol);
        As[lCol + 0][lRow] = av.x;
        As[lCol + 1][lRow] = av.y;
        As[lCol + 2][lRow] = av.z;
        As[lCol + 3][lRow] = av.w;
        float4 bv = *(const float4*)(Kh + (size_t)(n0 + lRow) * D_MODEL + k0 + lCol);
        Bs[lCol + 0][lRow] = bv.x;
        Bs[lCol + 1][lRow] = bv.y;
        Bs[lCol + 2][lRow] = bv.z;
        Bs[lCol + 3][lRow] = bv.w;
        __syncthreads();

#pragma unroll
        for (int k = 0; k < BK; k++) {
            float4 a0 = *(const float4*)&As[k][ty * 8];
            float4 a1 = *(const float4*)&As[k][ty * 8 + 4];
            float4 b0 = *(const float4*)&Bs[k][tx * 8];
            float4 b1 = *(const float4*)&Bs[k][tx * 8 + 4];
            float ar[8] = {a0.x, a0.y, a0.z, a0.w, a1.x, a1.y, a1.z, a1.w};
            float br[8] = {b0.x, b0.y, b0.z, b0.w, b1.x, b1.y, b1.z, b1.w};
#pragma unroll
            for (int i = 0; i < 8; i++)
#pragma unroll
                for (int j = 0; j < 8; j++)
                    acc[i][j] = fmaf(ar[i], br[j], acc[i][j]);
        }
        __syncthreads();
    }

    const int* mrow = mask + b * SEQ;
#pragma unroll
    for (int i = 0; i < 8; i++) {
        const int row = m0 + ty * 8 + i;
#pragma unroll
        for (int j = 0; j < 8; j += 4) {
            const int col = n0 + tx * 8 + j;
            float4 o;
            o.x = acc[i][j + 0] * scale + (float)mrow[col + 0] * NEG_INF_F;
            o.y = acc[i][j + 1] * scale + (float)mrow[col + 1] * NEG_INF_F;
            o.z = acc[i][j + 2] * scale + (float)mrow[col + 2] * NEG_INF_F;
            o.w = acc[i][j + 3] * scale + (float)mrow[col + 3] * NEG_INF_F;
            *(float4*)&Cb[(size_t)row * SEQ + col] = o;
        }
    }
}

// ---------------------------------------------------------------------------
// Softmax over last dim (SEQ=2048), one block (256 threads) per row.
// Values stay in registers: one read, one write.
// ---------------------------------------------------------------------------
__global__ __launch_bounds__(256) void softmax_kernel(float* __restrict__ attn)
{
    const size_t row = blockIdx.x;
    float* p = attn + row * (size_t)SEQ;
    const int tid = threadIdx.x;

    float4 v0 = ((const float4*)p)[2 * tid];
    float4 v1 = ((const float4*)p)[2 * tid + 1];

    float m = fmaxf(fmaxf(fmaxf(v0.x, v0.y), fmaxf(v0.z, v0.w)),
                    fmaxf(fmaxf(v1.x, v1.y), fmaxf(v1.z, v1.w)));
#pragma unroll
    for (int o = 16; o > 0; o >>= 1) m = fmaxf(m, __shfl_xor_sync(0xffffffffu, m, o));

    __shared__ float sred[8];
    const int w = tid >> 5, l = tid & 31;
    if (l == 0) sred[w] = m;
    __syncthreads();
    if (w == 0) {
        float t = (l < 8) ? sred[l] : -INFINITY;
#pragma unroll
        for (int o = 4; o > 0; o >>= 1) t = fmaxf(t, __shfl_xor_sync(0xffffffffu, t, o));
        if (l == 0) sred[0] = t;
    }
    __syncthreads();
    m = sred[0];
    __syncthreads();   // before reusing sred for the sum

    v0.x = __expf(v0.x - m); v0.y = __expf(v0.y - m);
    v0.z = __expf(v0.z - m); v0.w = __expf(v0.w - m);
    v1.x = __expf(v1.x - m); v1.y = __expf(v1.y - m);
    v1.z = __expf(v1.z - m); v1.w = __expf(v1.w - m);

    float s = v0.x + v0.y + v0.z + v0.w + v1.x + v1.y + v1.z + v1.w;
#pragma unroll
    for (int o = 16; o > 0; o >>= 1) s += __shfl_xor_sync(0xffffffffu, s, o);
    if (l == 0) sred[w] = s;
    __syncthreads();
    if (w == 0) {
        float t = (l < 8) ? sred[l] : 0.0f;
#pragma unroll
        for (int o = 4; o > 0; o >>= 1) t += __shfl_xor_sync(0xffffffffu, t, o);
        if (l == 0) sred[0] = t;
    }
    __syncthreads();
    const float inv = 1.0f / sred[0];

    v0.x *= inv; v0.y *= inv; v0.z *= inv; v0.w *= inv;
    v1.x *= inv; v1.y *= inv; v1.z *= inv; v1.w *= inv;
    ((float4*)p)[2 * tid] = v0;
    ((float4*)p)[2 * tid + 1] = v1;
}

// ---------------------------------------------------------------------------
// AV: per (b,h): ctx[b, i, h*64 + d] = sum_j attn[bh, i, j] * Vh[j, d]
// BM=128, BN=64 (=DEPTH), BK=32, 256 threads, 8x4 per thread.
// ---------------------------------------------------------------------------
__global__ __launch_bounds__(256) void av_kernel(
    const float* __restrict__ attn, const float* __restrict__ V,
    float* __restrict__ ctx)
{
    const int BM = 128, BN = 64, BK = 32;
    __shared__ __align__(16) float As[BK][BM];
    __shared__ __align__(16) float Bs[BK][BN];

    const int bh = blockIdx.z;
    const int b = bh / NUM_HEADS;
    const int h = bh % NUM_HEADS;
    const float* Ab = attn + (size_t)bh * SEQ * SEQ;
    const float* Vh = V + (size_t)b * SEQ * D_MODEL + h * DEPTH;

    const int m0 = blockIdx.y * BM;
    const int tid = threadIdx.x;
    const int tx = tid & 15;      // col group (4 cols each)
    const int ty = tid >> 4;      // row group (8 rows each)

    float acc[8][4];
#pragma unroll
    for (int i = 0; i < 8; i++)
#pragma unroll
        for (int j = 0; j < 4; j++) acc[i][j] = 0.0f;

    for (int k0 = 0; k0 < SEQ; k0 += BK) {
        // A tile: 128 rows x 32 k = 1024 float4s, 4 per thread
#pragma unroll
        for (int t = 0; t < 4; t++) {
            const int f4 = tid * 4 + t;        // 0..1023
            const int r = f4 >> 3;             // 0..127
            const int c4 = (f4 & 7) * 4;       // 0,4,...,28
            float4 av = *(const float4*)(Ab + (size_t)(m0 + r) * SEQ + k0 + c4);
            As[c4 + 0][r] = av.x;
            As[c4 + 1][r] = av.y;
            As[c4 + 2][r] = av.z;
            As[c4 + 3][r] = av.w;
        }
        // B tile: 32 k-rows x 64 cols = 512 float4s, 2 per thread
#pragma unroll
        for (int t = 0; t < 2; t++) {
            const int f4 = tid * 2 + t;        // 0..511
            const int r = f4 >> 4;             // 0..31
            const int c4 = (f4 & 15) * 4;      // 0..60
            float4 bv = *(const float4*)(Vh + (size_t)(k0 + r) * D_MODEL + c4);
            *(float4*)&Bs[r][c4] = bv;
        }
        __syncthreads();

#pragma unroll
        for (int k = 0; k < BK; k++) {
            float4 a0 = *(const float4*)&As[k][ty * 8];
            float4 a1 = *(const float4*)&As[k][ty * 8 + 4];
            float4 b0 = *(const float4*)&Bs[k][tx * 4];
            float ar[8] = {a0.x, a0.y, a0.z, a0.w, a1.x, a1.y, a1.z, a1.w};
            float br[4] = {b0.x, b0.y, b0.z, b0.w};
#pragma unroll
            for (int i = 0; i < 8; i++)
#pragma unroll
                for (int j = 0; j < 4; j++)
                    acc[i][j] = fmaf(ar[i], br[j], acc[i][j]);
        }
        __syncthreads();
    }

#pragma unroll
    for (int i = 0; i < 8; i++) {
        const int row = m0 + ty * 8 + i;
        float4 o = {acc[i][0], acc[i][1], acc[i][2], acc[i][3]};
        *(float4*)&ctx[(size_t)(b * SEQ + row) * D_MODEL + h * DEPTH + tx * 4] = o;
    }
}

// ---------------------------------------------------------------------------
// Launcher
// ---------------------------------------------------------------------------
extern "C" void kernel_launch(void* const* d_in, const int* in_sizes, int n_in,
                              void* d_out, int out_size)
{
    // metadata order: v, k, q, mask, Wq, bq, Wk, bk, Wv, bv, Wo, bo
    const float* v    = (const float*)d_in[0];
    const float* k    = (const float*)d_in[1];
    const float* q    = (const float*)d_in[2];
    const int*   mask = (const int*)  d_in[3];
    const float* Wq = (const float*)d_in[4];
    const float* bq = (const float*)d_in[5];
    const float* Wk = (const float*)d_in[6];
    const float* bk = (const float*)d_in[7];
    const float* Wv = (const float*)d_in[8];
    const float* bv = (const float*)d_in[9];
    const float* Wo = (const float*)d_in[10];
    const float* bo = (const float*)d_in[11];
    float* out = (float*)d_out;

    float *Qd = 0, *Kd = 0, *Vd = 0, *Ctx = 0, *AttnScratch = 0;
    cudaGetSymbolAddress((void**)&Qd, g_Q);
    cudaGetSymbolAddress((void**)&Kd, g_K);
    cudaGetSymbolAddress((void**)&Vd, g_V);
    cudaGetSymbolAddress((void**)&Ctx, g_ctx);
    cudaGetSymbolAddress((void**)&AttnScratch, g_attn);

    const size_t FINAL_ELEMS = (size_t)BS_ROWS * D_MODEL;                  // 4,194,304
    const size_t ATTN_ELEMS  = (size_t)BATCH * NUM_HEADS * SEQ * SEQ;      // 134,217,728

    // Reference returns (out, attn); if the harness packs both, attn follows out.
    float* attnp = ((size_t)out_size >= FINAL_ELEMS + ATTN_ELEMS)
                       ? (out + FINAL_ELEMS)
                       : AttnScratch;

    const dim3 gemm_grid(D_MODEL / 128, BS_ROWS / 128);   // (8, 32)
    sgemm_bias_kernel<<<gemm_grid, 256>>>(q, Wq, bq, Qd, BS_ROWS, D_MODEL, D_MODEL);
    sgemm_bias_kernel<<<gemm_grid, 256>>>(k, Wk, bk, Kd, BS_ROWS, D_MODEL, D_MODEL);
    sgemm_bias_kernel<<<gemm_grid, 256>>>(v, Wv, bv, Vd, BS_ROWS, D_MODEL, D_MODEL);

    const float scale = 0.125f;  // 1/sqrt(DEPTH)
    const dim3 lgrid(SEQ / 128, SEQ / 128, BATCH * NUM_HEADS);  // (16,16,32)
    logits_kernel<<<lgrid, 256>>>(Qd, Kd, mask, attnp, scale);

    softmax_kernel<<<(unsigned)(BATCH * NUM_HEADS * SEQ), 256>>>(attnp);

    const dim3 agrid(1, SEQ / 128, BATCH * NUM_HEADS);          // (1,16,32)
    av_kernel<<<agrid, 256>>>(attnp, Vd, Ctx);

    sgemm_bias_kernel<<<gemm_grid, 256>>>(Ctx, Wo, bo, out, BS_ROWS, D_MODEL, D_MODEL);
}

// round 3
// speedup vs baseline: 1.3475x; 1.3475x over previous
#include <cuda_runtime.h>
#include <cuda_fp16.h>
#include <math.h>
#include <stdint.h>
#include <stddef.h>

#define DM 1024
#define NH 16
#define DEPTH 64
#define BATCH 2
#define SEQ 2048
#define BS_ROWS 4096          /* BATCH*SEQ */
#define BH 32                 /* BATCH*NH */

// ---------------------------------------------------------------------------
// Scratch (__device__ globals; allocation-free rule)
// ---------------------------------------------------------------------------
__device__ __half g_Qhi[(size_t)BS_ROWS * DM];
__device__ __half g_Qlo[(size_t)BS_ROWS * DM];
__device__ __half g_Khi[(size_t)BS_ROWS * DM];
__device__ __half g_Klo[(size_t)BS_ROWS * DM];
__device__ __half g_Vhi[(size_t)BS_ROWS * DM];
__device__ __half g_Vlo[(size_t)BS_ROWS * DM];
__device__ __half g_Vthi[(size_t)BH * DEPTH * SEQ];   // [bh][d][s]
__device__ __half g_Vtlo[(size_t)BH * DEPTH * SEQ];
__device__ __half g_Cxhi[(size_t)BS_ROWS * DM];       // ctx split
__device__ __half g_Cxlo[(size_t)BS_ROWS * DM];
__device__ __half g_WThi[4][(size_t)DM * DM];         // W^T splits: q,k,v,o
__device__ __half g_WTlo[4][(size_t)DM * DM];
__device__ float  g_attn[(size_t)BH * SEQ * SEQ];     // fallback attn buffer
__device__ float  g_partial[(size_t)BH * SEQ * 16];   // per-(row, n-block) sums
__device__ float  g_rowsum[(size_t)BH * SEQ];

// ---------------------------------------------------------------------------
// Helpers
// ---------------------------------------------------------------------------
__device__ __forceinline__ float residf(float x) {
    return x - __half2float(__float2half_rn(x));
}
#define LDU32(p) (*(const uint32_t*)(p))

__device__ __forceinline__ void mma16816(float4& d,
    uint32_t a0, uint32_t a1, uint32_t a2, uint32_t a3,
    uint32_t b0, uint32_t b1)
{
    asm volatile(
        "mma.sync.aligned.m16n8k16.row.col.f32.f16.f16.f32 "
        "{%0,%1,%2,%3},{%4,%5,%6,%7},{%8,%9},{%0,%1,%2,%3};\n"
        : "+f"(d.x), "+f"(d.y), "+f"(d.z), "+f"(d.w)
        : "r"(a0), "r"(a1), "r"(a2), "r"(a3), "r"(b0), "r"(b1));
}

// ---------------------------------------------------------------------------
// Weight transpose+split: W[K][N] fp32 -> WT_hi/lo[N][K] halves
// ---------------------------------------------------------------------------
__global__ __launch_bounds__(256) void transpose_split_kernel(
    const float* __restrict__ W, __half* __restrict__ Thi, __half* __restrict__ Tlo)
{
    __shared__ float tile[32][33];
    const int k0 = blockIdx.y * 32, n0 = blockIdx.x * 32;
    const int tx = threadIdx.x & 31, ty = threadIdx.x >> 5;
#pragma unroll
    for (int i = 0; i < 4; i++) {
        int kk = ty + i * 8;
        tile[kk][tx] = W[(size_t)(k0 + kk) * DM + n0 + tx];
    }
    __syncthreads();
#pragma unroll
    for (int i = 0; i < 4; i++) {
        int nn = ty + i * 8;
        float x = tile[tx][nn];
        __half hi = __float2half_rn(x);
        Thi[(size_t)(n0 + nn) * DM + k0 + tx] = hi;
        Tlo[(size_t)(n0 + nn) * DM + k0 + tx] =
            __float2half_rn(x - __half2float(hi));
    }
}

// ---------------------------------------------------------------------------
// V transpose (halves): Vhi/lo [4096][1024] -> Vt [bh][64][2048]
// ---------------------------------------------------------------------------
__global__ __launch_bounds__(256) void transpose_v_kernel(
    const __half* __restrict__ Vhi, const __half* __restrict__ Vlo,
    __half* __restrict__ Thi, __half* __restrict__ Tlo)
{
    __shared__ __half thi[32][33], tlo[32][33];
    const int n0 = blockIdx.x * 32;    // d_model col
    const int s0 = blockIdx.y * 32;    // global row (0..4095)
    const int tx = threadIdx.x & 31, ty = threadIdx.x >> 5;
#pragma unroll
    for (int i = 0; i < 4; i++) {
        int r = ty + i * 8;
        thi[r][tx] = Vhi[(size_t)(s0 + r) * DM + n0 + tx];
        tlo[r][tx] = Vlo[(size_t)(s0 + r) * DM + n0 + tx];
    }
    __syncthreads();
    const int b = s0 >> 11;
#pragma unroll
    for (int i = 0; i < 4; i++) {
        int nn = ty + i * 8;
        int gn = n0 + nn;
        int h = gn >> 6, d = gn & 63;
        size_t orow = ((size_t)(b * NH + h) * DEPTH + d) * SEQ + (s0 & 2047) + tx;
        Thi[orow] = thi[tx][nn];
        Tlo[orow] = tlo[tx][nn];
    }
}

// ---------------------------------------------------------------------------
// Split-fp16 GEMM: C[M=4096,N=1024] = A[4096,1024] @ Bt^T + bias
//   Bt given as [N][K] half hi/lo. BM=BN=128, BK=32. 8 warps (2m x 4n).
//   CONV_A: A is fp32 (split in-kernel). OUT_F32: write fp32 C, else half split.
// ---------------------------------------------------------------------------
template<bool CONV_A, bool OUT_F32>
__global__ __launch_bounds__(256, 1) void gemm_kernel(
    const float* __restrict__ Af,
    const __half* __restrict__ AhiG, const __half* __restrict__ AloG,
    const __half* __restrict__ BhiG, const __half* __restrict__ BloG,
    const float* __restrict__ bias,
    float* __restrict__ Cf, __half* __restrict__ Chi, __half* __restrict__ Clo)
{
    __shared__ __half As_hi[128][40], As_lo[128][40];
    __shared__ __half Bs_hi[128][40], Bs_lo[128][40];

    const int tid = threadIdx.x;
    const int m0 = blockIdx.y * 128, n0 = blockIdx.x * 128;
    const int lane = tid & 31, wid = tid >> 5;
    const int wm = wid >> 2, wn = wid & 3;
    const int grp = lane >> 2, tig = lane & 3;

    float4 acc[4][4];
#pragma unroll
    for (int i = 0; i < 4; i++)
#pragma unroll
        for (int j = 0; j < 4; j++) acc[i][j] = make_float4(0.f, 0.f, 0.f, 0.f);

    for (int k0 = 0; k0 < DM; k0 += 32) {
        if (CONV_A) {
#pragma unroll
            for (int t = 0; t < 4; t++) {
                int id = tid * 4 + t;             // 0..1023
                int r = id >> 3, c4 = (id & 7) * 4;
                float4 v = *(const float4*)(Af + (size_t)(m0 + r) * DM + k0 + c4);
                *(__half2*)&As_hi[r][c4]     = __floats2half2_rn(v.x, v.y);
                *(__half2*)&As_hi[r][c4 + 2] = __floats2half2_rn(v.z, v.w);
                *(__half2*)&As_lo[r][c4]     = __floats2half2_rn(residf(v.x), residf(v.y));
                *(__half2*)&As_lo[r][c4 + 2] = __floats2half2_rn(residf(v.z), residf(v.w));
            }
        } else {
#pragma unroll
            for (int t = 0; t < 2; t++) {
                int id = tid * 2 + t;             // 0..511
                int r = id >> 2, q = id & 3;
                uint4 vh = *(const uint4*)(AhiG + (size_t)(m0 + r) * DM + k0 + q * 8);
                *(uint2*)&As_hi[r][q * 8]     = make_uint2(vh.x, vh.y);
                *(uint2*)&As_hi[r][q * 8 + 4] = make_uint2(vh.z, vh.w);
                uint4 vl = *(const uint4*)(AloG + (size_t)(m0 + r) * DM + k0 + q * 8);
                *(uint2*)&As_lo[r][q * 8]     = make_uint2(vl.x, vl.y);
                *(uint2*)&As_lo[r][q * 8 + 4] = make_uint2(vl.z, vl.w);
            }
        }
#pragma unroll
        for (int t = 0; t < 2; t++) {
            int id = tid * 2 + t;
            int r = id >> 2, q = id & 3;
            uint4 vh = *(const uint4*)(BhiG + (size_t)(n0 + r) * DM + k0 + q * 8);
            *(uint2*)&Bs_hi[r][q * 8]     = make_uint2(vh.x, vh.y);
            *(uint2*)&Bs_hi[r][q * 8 + 4] = make_uint2(vh.z, vh.w);
            uint4 vl = *(const uint4*)(BloG + (size_t)(n0 + r) * DM + k0 + q * 8);
            *(uint2*)&Bs_lo[r][q * 8]     = make_uint2(vl.x, vl.y);
            *(uint2*)&Bs_lo[r][q * 8 + 4] = make_uint2(vl.z, vl.w);
        }
        __syncthreads();

#pragma unroll
        for (int kk = 0; kk < 2; kk++) {
            const int kb = kk * 16 + tig * 2;
            uint32_t ah[4][4], al[4][4];
#pragma unroll
            for (int mt = 0; mt < 4; mt++) {
                int r = wm * 64 + mt * 16 + grp;
                ah[mt][0] = LDU32(&As_hi[r][kb]);
                ah[mt][1] = LDU32(&As_hi[r + 8][kb]);
                ah[mt][2] = LDU32(&As_hi[r][kb + 8]);
                ah[mt][3] = LDU32(&As_hi[r + 8][kb + 8]);
                al[mt][0] = LDU32(&As_lo[r][kb]);
                al[mt][1] = LDU32(&As_lo[r + 8][kb]);
                al[mt][2] = LDU32(&As_lo[r][kb + 8]);
                al[mt][3] = LDU32(&As_lo[r + 8][kb + 8]);
            }
            uint32_t bhv[4][2], blv[4][2];
#pragma unroll
            for (int nt = 0; nt < 4; nt++) {
                int c = wn * 32 + nt * 8 + grp;
                bhv[nt][0] = LDU32(&Bs_hi[c][kb]);
                bhv[nt][1] = LDU32(&Bs_hi[c][kb + 8]);
                blv[nt][0] = LDU32(&Bs_lo[c][kb]);
                blv[nt][1] = LDU32(&Bs_lo[c][kb + 8]);
            }
#pragma unroll
            for (int mt = 0; mt < 4; mt++)
#pragma unroll
                for (int nt = 0; nt < 4; nt++) {
                    mma16816(acc[mt][nt], ah[mt][0], ah[mt][1], ah[mt][2], ah[mt][3],
                             bhv[nt][0], bhv[nt][1]);
                    mma16816(acc[mt][nt], ah[mt][0], ah[mt][1], ah[mt][2], ah[mt][3],
                             blv[nt][0], blv[nt][1]);
                    mma16816(acc[mt][nt], al[mt][0], al[mt][1], al[mt][2], al[mt][3],
                             bhv[nt][0], bhv[nt][1]);
                }
        }
        __syncthreads();
    }

#pragma unroll
    for (int mt = 0; mt < 4; mt++) {
        int r = m0 + wm * 64 + mt * 16 + grp;
#pragma unroll
        for (int nt = 0; nt < 4; nt++) {
            int c = n0 + wn * 32 + nt * 8 + tig * 2;
            float bx = bias[c], by = bias[c + 1];
            float x0 = acc[mt][nt].x + bx, x1 = acc[mt][nt].y + by;
            float x2 = acc[mt][nt].z + bx, x3 = acc[mt][nt].w + by;
            if (OUT_F32) {
                *(float2*)&Cf[(size_t)r * DM + c]       = make_float2(x0, x1);
                *(float2*)&Cf[(size_t)(r + 8) * DM + c] = make_float2(x2, x3);
            } else {
                *(__half2*)&Chi[(size_t)r * DM + c]       = __floats2half2_rn(x0, x1);
                *(__half2*)&Chi[(size_t)(r + 8) * DM + c] = __floats2half2_rn(x2, x3);
                *(__half2*)&Clo[(size_t)r * DM + c]       = __floats2half2_rn(residf(x0), residf(x1));
                *(__half2*)&Clo[(size_t)(r + 8) * DM + c] = __floats2half2_rn(residf(x2), residf(x3));
            }
        }
    }
}

// ---------------------------------------------------------------------------
// Logits: attn[bh,i,j] = mask[b,j] ? 0 : exp(0.125 * Q_h[i,:].K_h[j,:])
// Writes deterministic per-(row, n-block) partial sums.
// BM=BN=128, K=DEPTH=64 (single tile). Dynamic smem.
// ---------------------------------------------------------------------------
#define LP 72
#define LOGITS_SMEM (4 * 128 * LP * 2 + 128 * 4 * 4)

__global__ __launch_bounds__(256, 1) void logits_kernel(
    const __half* __restrict__ Qhi, const __half* __restrict__ Qlo,
    const __half* __restrict__ Khi, const __half* __restrict__ Klo,
    const int* __restrict__ mask, float* __restrict__ attn,
    float* __restrict__ partial)
{
    extern __shared__ __half sm[];
    __half (*Qh)[LP] = (__half(*)[LP])sm;
    __half (*Ql)[LP] = (__half(*)[LP])(sm + 128 * LP);
    __half (*Kh)[LP] = (__half(*)[LP])(sm + 2 * 128 * LP);
    __half (*Kl)[LP] = (__half(*)[LP])(sm + 3 * 128 * LP);
    float* sums = (float*)(sm + 4 * 128 * LP);   // [128][4]

    const int tid = threadIdx.x;
    const int n0 = blockIdx.x * 128, m0 = blockIdx.y * 128;
    const int bh = blockIdx.z, b = bh >> 4, h = bh & 15;
    const size_t hbase = (size_t)b * SEQ * DM + h * 64;

#pragma unroll
    for (int t = 0; t < 16; t++) {
        int id = tid + 256 * t;
        int arr = id >> 10, rem = id & 1023;
        int r = rem >> 3, q = rem & 7;
        const __half* src = (arr == 0) ? Qhi : (arr == 1) ? Qlo : (arr == 2) ? Khi : Klo;
        __half (*dst)[LP] = (arr == 0) ? Qh : (arr == 1) ? Ql : (arr == 2) ? Kh : Kl;
        int rowoff = (arr < 2) ? m0 : n0;
        uint4 v = *(const uint4*)(src + hbase + (size_t)(rowoff + r) * DM + q * 8);
        *(uint2*)&dst[r][q * 8]     = make_uint2(v.x, v.y);
        *(uint2*)&dst[r][q * 8 + 4] = make_uint2(v.z, v.w);
    }
    __syncthreads();

    const int lane = tid & 31, wid = tid >> 5;
    const int wm = wid >> 2, wn = wid & 3;
    const int grp = lane >> 2, tig = lane & 3;

    float4 acc[4][4];
#pragma unroll
    for (int i = 0; i < 4; i++)
#pragma unroll
        for (int j = 0; j < 4; j++) acc[i][j] = make_float4(0.f, 0.f, 0.f, 0.f);

#pragma unroll
    for (int ks = 0; ks < 4; ks++) {
        const int kb = ks * 16 + tig * 2;
        uint32_t ah[4][4], al[4][4];
#pragma unroll
        for (int mt = 0; mt < 4; mt++) {
            int r = wm * 64 + mt * 16 + grp;
            ah[mt][0] = LDU32(&Qh[r][kb]);
            ah[mt][1] = LDU32(&Qh[r + 8][kb]);
            ah[mt][2] = LDU32(&Qh[r][kb + 8]);
            ah[mt][3] = LDU32(&Qh[r + 8][kb + 8]);
            al[mt][0] = LDU32(&Ql[r][kb]);
            al[mt][1] = LDU32(&Ql[r + 8][kb]);
            al[mt][2] = LDU32(&Ql[r][kb + 8]);
            al[mt][3] = LDU32(&Ql[r + 8][kb + 8]);
        }
        uint32_t bhv[4][2], blv[4][2];
#pragma unroll
        for (int nt = 0; nt < 4; nt++) {
            int c = wn * 32 + nt * 8 + grp;
            bhv[nt][0] = LDU32(&Kh[c][kb]);
            bhv[nt][1] = LDU32(&Kh[c][kb + 8]);
            blv[nt][0] = LDU32(&Kl[c][kb]);
            blv[nt][1] = LDU32(&Kl[c][kb + 8]);
        }
#pragma unroll
        for (int mt = 0; mt < 4; mt++)
#pragma unroll
            for (int nt = 0; nt < 4; nt++) {
                mma16816(acc[mt][nt], ah[mt][0], ah[mt][1], ah[mt][2], ah[mt][3],
                         bhv[nt][0], bhv[nt][1]);
                mma16816(acc[mt][nt], ah[mt][0], ah[mt][1], ah[mt][2], ah[mt][3],
                         blv[nt][0], blv[nt][1]);
                mma16816(acc[mt][nt], al[mt][0], al[mt][1], al[mt][2], al[mt][3],
                         bhv[nt][0], bhv[nt][1]);
            }
    }

    const int* mrow = mask + b * SEQ;
    float rs0[4], rs1[4];
#pragma unroll
    for (int mt = 0; mt < 4; mt++) { rs0[mt] = 0.f; rs1[mt] = 0.f; }

#pragma unroll
    for (int mt = 0; mt < 4; mt++) {
        int r = m0 + wm * 64 + mt * 16 + grp;
        float* out0 = attn + ((size_t)bh * SEQ + r) * SEQ;
        float* out1 = out0 + (size_t)8 * SEQ;
#pragma unroll
        for (int nt = 0; nt < 4; nt++) {
            int j = n0 + wn * 32 + nt * 8 + tig * 2;
            int mk0 = mrow[j], mk1 = mrow[j + 1];
            float4 a = acc[mt][nt];
            float p0 = mk0 ? 0.f : __expf(a.x * 0.125f);
            float p1 = mk1 ? 0.f : __expf(a.y * 0.125f);
            float p2 = mk0 ? 0.f : __expf(a.z * 0.125f);
            float p3 = mk1 ? 0.f : __expf(a.w * 0.125f);
            *(float2*)(out0 + j) = make_float2(p0, p1);
            *(float2*)(out1 + j) = make_float2(p2, p3);
            rs0[mt] += p0 + p1;
            rs1[mt] += p2 + p3;
        }
    }
    // reduce across tig (4 lanes of same row), then across the 4 n-warps via smem
#pragma unroll
    for (int mt = 0; mt < 4; mt++) {
        float s0 = rs0[mt], s1 = rs1[mt];
        s0 += __shfl_xor_sync(0xffffffffu, s0, 1);
        s0 += __shfl_xor_sync(0xffffffffu, s0, 2);
        s1 += __shfl_xor_sync(0xffffffffu, s1, 1);
        s1 += __shfl_xor_sync(0xffffffffu, s1, 2);
        if (tig == 0) {
            int rl = wm * 64 + mt * 16 + grp;
            sums[(size_t)rl * 4 + wn] = s0;
            sums[(size_t)(rl + 8) * 4 + wn] = s1;
        }
    }
    __syncthreads();
    if (tid < 128) {
        float tot = (sums[tid * 4 + 0] + sums[tid * 4 + 1]) +
                    (sums[tid * 4 + 2] + sums[tid * 4 + 3]);
        partial[((size_t)bh * SEQ + m0 + tid) * 16 + blockIdx.x] = tot;
    }
}

// Deterministic finish of row sums.
__global__ __launch_bounds__(256) void reduce_sums_kernel(
    const float* __restrict__ partial, float* __restrict__ rowsum)
{
    int i = blockIdx.x * 256 + threadIdx.x;        // 0..65535
    const float4* p = (const float4*)(partial + (size_t)i * 16);
    float4 a = p[0], b = p[1], c = p[2], d = p[3];
    float s = ((a.x + a.y) + (a.z + a.w)) + ((b.x + b.y) + (b.z + b.w)) +
              ((c.x + c.y) + (c.z + c.w)) + ((d.x + d.y) + (d.z + d.w));
    rowsum[i] = s;
}

// ---------------------------------------------------------------------------
// AV: normalize attn in-place (p = e / rowsum), write back, ctx = P @ V_h.
// BM=128, BN=64, BK=64. 8 warps (2m x 4n, warp tile 64x16). Dynamic smem.
// ---------------------------------------------------------------------------
#define AV_SMEM (2 * 128 * LP * 2 + 2 * 64 * LP * 2 + 128 * 4)

__global__ __launch_bounds__(256, 1) void av_kernel(
    float* __restrict__ attn,
    const __half* __restrict__ Vthi, const __half* __restrict__ Vtlo,
    const float* __restrict__ rowsum,
    __half* __restrict__ Chi, __half* __restrict__ Clo)
{
    extern __shared__ char smraw[];
    __half (*Ah)[LP] = (__half(*)[LP])smraw;
    __half (*Al)[LP] = (__half(*)[LP])(smraw + 128 * LP * 2);
    __half (*Vh)[LP] = (__half(*)[LP])(smraw + 2 * 128 * LP * 2);
    __half (*Vl)[LP] = (__half(*)[LP])(smraw + 2 * 128 * LP * 2 + 64 * LP * 2);
    float* sinv = (float*)(smraw + 2 * 128 * LP * 2 + 2 * 64 * LP * 2);

    const int tid = threadIdx.x;
    const int m0 = blockIdx.x * 128;
    const int bh = blockIdx.y, b = bh >> 4, h = bh & 15;

    if (tid < 128) sinv[tid] = 1.0f / rowsum[(size_t)bh * SEQ + m0 + tid];
    __syncthreads();

    const int lane = tid & 31, wid = tid >> 5;
    const int wm = wid >> 2, wn = wid & 3;
    const int grp = lane >> 2, tig = lane & 3;

    float4 acc[4][2];
#pragma unroll
    for (int i = 0; i < 4; i++)
#pragma unroll
        for (int j = 0; j < 2; j++) acc[i][j] = make_float4(0.f, 0.f, 0.f, 0.f);

    float* Abase = attn + ((size_t)bh * SEQ + m0) * SEQ;
    const size_t vtb = (size_t)bh * DEPTH * SEQ;

    for (int k0 = 0; k0 < SEQ; k0 += 64) {
#pragma unroll
        for (int t = 0; t < 8; t++) {
            int id = tid * 8 + t;              // 0..2047
            int r = id >> 4, c4 = (id & 15) * 4;
            float4 v = *(float4*)(Abase + (size_t)r * SEQ + k0 + c4);
            float iv = sinv[r];
            v.x *= iv; v.y *= iv; v.z *= iv; v.w *= iv;
            *(float4*)(Abase + (size_t)r * SEQ + k0 + c4) = v;
            *(__half2*)&Ah[r][c4]     = __floats2half2_rn(v.x, v.y);
            *(__half2*)&Ah[r][c4 + 2] = __floats2half2_rn(v.z, v.w);
            *(__half2*)&Al[r][c4]     = __floats2half2_rn(residf(v.x), residf(v.y));
            *(__half2*)&Al[r][c4 + 2] = __floats2half2_rn(residf(v.z), residf(v.w));
        }
#pragma unroll
        for (int t = 0; t < 4; t++) {
            int id = tid * 4 + t;              // 0..1023
            int arr = id >> 9, rem = id & 511;
            int r = rem >> 3, q = rem & 7;
            const __half* src = arr ? Vtlo : Vthi;
            __half (*dst)[LP] = arr ? Vl : Vh;
            uint4 v = *(const uint4*)(src + vtb + (size_t)r * SEQ + k0 + q * 8);
            *(uint2*)&dst[r][q * 8]     = make_uint2(v.x, v.y);
            *(uint2*)&dst[r][q * 8 + 4] = make_uint2(v.z, v.w);
        }
        __syncthreads();

#pragma unroll
        for (int ks = 0; ks < 4; ks++) {
            const int kb = ks * 16 + tig * 2;
            uint32_t ah[4][4], al[4][4];
#pragma unroll
            for (int mt = 0; mt < 4; mt++) {
                int r = wm * 64 + mt * 16 + grp;
                ah[mt][0] = LDU32(&Ah[r][kb]);
                ah[mt][1] = LDU32(&Ah[r + 8][kb]);
                ah[mt][2] = LDU32(&Ah[r][kb + 8]);
                ah[mt][3] = LDU32(&Ah[r + 8][kb + 8]);
                al[mt][0] = LDU32(&Al[r][kb]);
                al[mt][1] = LDU32(&Al[r + 8][kb]);
                al[mt][2] = LDU32(&Al[r][kb + 8]);
                al[mt][3] = LDU32(&Al[r + 8][kb + 8]);
            }
            uint32_t bhv[2][2], blv[2][2];
#pragma unroll
            for (int nt = 0; nt < 2; nt++) {
                int c = wn * 16 + nt * 8 + grp;
                bhv[nt][0] = LDU32(&Vh[c][kb]);
                bhv[nt][1] = LDU32(&Vh[c][kb + 8]);
                blv[nt][0] = LDU32(&Vl[c][kb]);
                blv[nt][1] = LDU32(&Vl[c][kb + 8]);
            }
#pragma unroll
            for (int mt = 0; mt < 4; mt++)
#pragma unroll
                for (int nt = 0; nt < 2; nt++) {
                    mma16816(acc[mt][nt], ah[mt][0], ah[mt][1], ah[mt][2], ah[mt][3],
                             bhv[nt][0], bhv[nt][1]);
                    mma16816(acc[mt][nt], ah[mt][0], ah[mt][1], ah[mt][2], ah[mt][3],
                             blv[nt][0], blv[nt][1]);
                    mma16816(acc[mt][nt], al[mt][0], al[mt][1], al[mt][2], al[mt][3],
                             bhv[nt][0], bhv[nt][1]);
                }
        }
        __syncthreads();
    }

#pragma unroll
    for (int mt = 0; mt < 4; mt++) {
        int r = m0 + wm * 64 + mt * 16 + grp;
#pragma unroll
        for (int nt = 0; nt < 2; nt++) {
            int d = wn * 16 + nt * 8 + tig * 2;
            size_t o = ((size_t)(b * SEQ + r)) * DM + h * 64 + d;
            float x0 = acc[mt][nt].x, x1 = acc[mt][nt].y;
            float x2 = acc[mt][nt].z, x3 = acc[mt][nt].w;
            *(__half2*)&Chi[o]            = __floats2half2_rn(x0, x1);
            *(__half2*)&Chi[o + 8 * DM]   = __floats2half2_rn(x2, x3);
            *(__half2*)&Clo[o]            = __floats2half2_rn(residf(x0), residf(x1));
            *(__half2*)&Clo[o + 8 * DM]   = __floats2half2_rn(residf(x2), residf(x3));
        }
    }
}

// ---------------------------------------------------------------------------
// Launcher
// ---------------------------------------------------------------------------
extern "C" void kernel_launch(void* const* d_in, const int* in_sizes, int n_in,
                              void* d_out, int out_size)
{
    const float* v    = (const float*)d_in[0];
    const float* k    = (const float*)d_in[1];
    const float* q    = (const float*)d_in[2];
    const int*   mask = (const int*)  d_in[3];
    const float* Wq = (const float*)d_in[4];
    const float* bq = (const float*)d_in[5];
    const float* Wk = (const float*)d_in[6];
    const float* bk = (const float*)d_in[7];
    const float* Wv = (const float*)d_in[8];
    const float* bv = (const float*)d_in[9];
    const float* Wo = (const float*)d_in[10];
    const float* bo = (const float*)d_in[11];
    float* out = (float*)d_out;

    __half *Qhi, *Qlo, *Khi, *Klo, *Vhi, *Vlo, *Vthi, *Vtlo, *Cxhi, *Cxlo;
    __half (*WThi)[(size_t)DM * DM];
    __half (*WTlo)[(size_t)DM * DM];
    float *attnScratch, *partialp, *rowsump;
    cudaGetSymbolAddress((void**)&Qhi, g_Qhi);
    cudaGetSymbolAddress((void**)&Qlo, g_Qlo);
    cudaGetSymbolAddress((void**)&Khi, g_Khi);
    cudaGetSymbolAddress((void**)&Klo, g_Klo);
    cudaGetSymbolAddress((void**)&Vhi, g_Vhi);
    cudaGetSymbolAddress((void**)&Vlo, g_Vlo);
    cudaGetSymbolAddress((void**)&Vthi, g_Vthi);
    cudaGetSymbolAddress((void**)&Vtlo, g_Vtlo);
    cudaGetSymbolAddress((void**)&Cxhi, g_Cxhi);
    cudaGetSymbolAddress((void**)&Cxlo, g_Cxlo);
    cudaGetSymbolAddress((void**)&WThi, g_WThi);
    cudaGetSymbolAddress((void**)&WTlo, g_WTlo);
    cudaGetSymbolAddress((void**)&attnScratch, g_attn);
    cudaGetSymbolAddress((void**)&partialp, g_partial);
    cudaGetSymbolAddress((void**)&rowsump, g_rowsum);

    cudaFuncSetAttribute(logits_kernel,
                         cudaFuncAttributeMaxDynamicSharedMemorySize, LOGITS_SMEM);
    cudaFuncSetAttribute(av_kernel,
                         cudaFuncAttributeMaxDynamicSharedMemorySize, AV_SMEM);

    const size_t FINAL_ELEMS = (size_t)BS_ROWS * DM;
    const size_t ATTN_ELEMS  = (size_t)BH * SEQ * SEQ;
    float* attnp = ((size_t)out_size >= FINAL_ELEMS + ATTN_ELEMS)
                       ? (out + FINAL_ELEMS) : attnScratch;

    const dim3 tgrid(32, 32);
    transpose_split_kernel<<<tgrid, 256>>>(Wq, WThi[0], WTlo[0]);
    transpose_split_kernel<<<tgrid, 256>>>(Wk, WThi[1], WTlo[1]);
    transpose_split_kernel<<<tgrid, 256>>>(Wv, WThi[2], WTlo[2]);
    transpose_split_kernel<<<tgrid, 256>>>(Wo, WThi[3], WTlo[3]);

    const dim3 ggrid(8, 32);
    gemm_kernel<true, false><<<ggrid, 256>>>(q, nullptr, nullptr,
        WThi[0], WTlo[0], bq, nullptr, Qhi, Qlo);
    gemm_kernel<true, false><<<ggrid, 256>>>(k, nullptr, nullptr,
        WThi[1], WTlo[1], bk, nullptr, Khi, Klo);
    gemm_kernel<true, false><<<ggrid, 256>>>(v, nullptr, nullptr,
        WThi[2], WTlo[2], bv, nullptr, Vhi, Vlo);

    transpose_v_kernel<<<dim3(32, 128), 256>>>(Vhi, Vlo, Vthi, Vtlo);

    logits_kernel<<<dim3(16, 16, BH), 256, LOGITS_SMEM>>>(
        Qhi, Qlo, Khi, Klo, mask, attnp, partialp);

    reduce_sums_kernel<<<(BH * SEQ) / 256, 256>>>(partialp, rowsump);

    av_kernel<<<dim3(16, BH), 256, AV_SMEM>>>(
        attnp, Vthi, Vtlo, rowsump, Cxhi, Cxlo);

    gemm_kernel<false, true><<<ggrid, 256>>>(nullptr, Cxhi, Cxlo,
        WThi[3], WTlo[3], bo, out, nullptr, nullptr);
}